// round 3
// baseline (speedup 1.0000x reference)
#include <cuda_runtime.h>
#include <cstdint>

// Covariance pooling: y[b] = (1/M) X Xᵀ - μ μᵀ, X = x[b] as [C=128, M=4096].
// Single fused kernel, tf32 mma.sync + ldmatrix fragments.
// 128 CTAs = 64 batches x 2 output row-slabs (64 rows each). Each CTA streams
// the full [128 x 4096] batch through SMEM k-tiles (double-buffered, 2-ahead
// register prefetch), computes its 64x128 slab of the Gram on tensor cores,
// accumulates exact fp32 row sums on the side, and applies mean subtraction
// in the epilogue. No scratch, no second kernel.

#define DINLINE __device__ __forceinline__

static constexpr int Bn = 64;
static constexpr int Cn = 128;
static constexpr int Mn = 4096;
static constexpr int KT = 32;             // k floats per tile
static constexpr int NKT = Mn / KT;       // 128 tiles
static constexpr int PAD = 36;            // floats per SMEM row (144 B)
static constexpr int PADB = PAD * 4;

DINLINE void mma_tf32(float d[4], const uint32_t a[4], uint32_t b0, uint32_t b1) {
    asm volatile(
        "mma.sync.aligned.m16n8k8.row.col.f32.tf32.tf32.f32 "
        "{%0,%1,%2,%3}, {%4,%5,%6,%7}, {%8,%9}, {%0,%1,%2,%3};"
        : "+f"(d[0]), "+f"(d[1]), "+f"(d[2]), "+f"(d[3])
        : "r"(a[0]), "r"(a[1]), "r"(a[2]), "r"(a[3]), "r"(b0), "r"(b1));
}
DINLINE uint32_t to_tf32(float v) {
    uint32_t u;
    asm("cvt.rna.tf32.f32 %0, %1;" : "=r"(u) : "f"(v));
    return u;
}
DINLINE void ldsm_x4(uint32_t r[4], uint32_t addr) {
    asm volatile("ldmatrix.sync.aligned.m8n8.x4.shared.b16 {%0,%1,%2,%3}, [%4];"
                 : "=r"(r[0]), "=r"(r[1]), "=r"(r[2]), "=r"(r[3]) : "r"(addr));
}
DINLINE uint32_t smem_u32(const void* p) {
    uint32_t a;
    asm("{ .reg .u64 t; cvta.to.shared.u64 t, %1; cvt.u32.u64 %0, t; }"
        : "=r"(a) : "l"(p));
    return a;
}

__global__ __launch_bounds__(256, 1)
void covpool_fused(const float* __restrict__ x, float* __restrict__ y) {
    __shared__ uint32_t buf[2][Cn * PAD];
    __shared__ float mu[Cn];

    const int t    = threadIdx.x;
    const int warp = t >> 5;
    const int lane = t & 31;
    const int cta  = blockIdx.x;          // 0..127
    const int h    = cta & 1;             // output row-slab
    const int b    = cta >> 1;

    // loader mapping: 2 threads per row, 16 floats each
    const int row  = t >> 1;
    const int coff = (t & 1) * 16;
    const float* src = x + (size_t)b * Cn * Mn + (size_t)row * Mn + coff;

    // warp tile: 32 (m) x 32 (n)
    const int wm = h * 64 + (warp & 1) * 32;
    const int wn = (warp >> 1) * 32;
    const int g  = lane >> 2;
    const int tg = lane & 3;

    // ldmatrix per-lane byte offsets (relative to buffer base)
    const uint32_t aoff = (uint32_t)((wm + (lane & 15)) * PADB + (lane >> 4) * 16);
    const uint32_t boff = (uint32_t)((wn + (lane & 7) + (lane >> 4) * 8) * PADB
                                     + ((lane >> 3) & 1) * 16);
    const uint32_t sbase0 = smem_u32(&buf[0][0]);
    const uint32_t sbase1 = smem_u32(&buf[1][0]);

    float acc[2][4][4];
#pragma unroll
    for (int im = 0; im < 2; im++)
#pragma unroll
        for (int in = 0; in < 4; in++)
#pragma unroll
            for (int j = 0; j < 4; j++) acc[im][in][j] = 0.0f;

    float rowsum = 0.0f;
    float4 R[2][4];                        // 2-deep register staging

    // prologue: LDG tiles 0,1; STS tile 0
#pragma unroll
    for (int i = 0; i < 4; i++) R[0][i] = __ldg((const float4*)(src + i * 4));
#pragma unroll
    for (int i = 0; i < 4; i++) R[1][i] = __ldg((const float4*)(src + KT + i * 4));
    {
        uint32_t* dst = &buf[0][row * PAD + coff];
#pragma unroll
        for (int i = 0; i < 4; i++) {
            float4 v = R[0][i];
            rowsum += v.x + v.y + v.z + v.w;
            uint4 u = { to_tf32(v.x), to_tf32(v.y), to_tf32(v.z), to_tf32(v.w) };
            *(uint4*)(dst + i * 4) = u;
        }
    }
    __syncthreads();

    for (int kt = 0; kt < NKT; kt++) {
        const int cur = kt & 1;
        const int nxt = cur ^ 1;
        // stage tile kt+1 into buf[nxt]
        if (kt + 1 < NKT) {
            uint32_t* dst = &buf[nxt][row * PAD + coff];
#pragma unroll
            for (int i = 0; i < 4; i++) {
                float4 v = R[nxt][i];
                rowsum += v.x + v.y + v.z + v.w;
                uint4 u = { to_tf32(v.x), to_tf32(v.y), to_tf32(v.z), to_tf32(v.w) };
                *(uint4*)(dst + i * 4) = u;
            }
        }
        // prefetch tile kt+2 into R[cur]
        if (kt + 2 < NKT) {
            const float* nsrc = src + (kt + 2) * KT;
#pragma unroll
            for (int i = 0; i < 4; i++)
                R[cur][i] = __ldg((const float4*)(nsrc + i * 4));
        }
        // compute on buf[cur]
        const uint32_t base = cur ? sbase1 : sbase0;
#pragma unroll
        for (int ks = 0; ks < 4; ks++) {
            const uint32_t k0 = ks * 32;   // bytes
            uint32_t a0[4], a1[4], b0[4], b1[4];
            ldsm_x4(a0, base + aoff + k0);
            ldsm_x4(a1, base + aoff + 16 * PADB + k0);
            ldsm_x4(b0, base + boff + k0);
            ldsm_x4(b1, base + boff + 16 * PADB + k0);
            // b-frag pairs: n-tiles at wn+0, wn+8, wn+16, wn+24
            mma_tf32(acc[0][0], a0, b0[0], b0[1]);
            mma_tf32(acc[0][1], a0, b0[2], b0[3]);
            mma_tf32(acc[0][2], a0, b1[0], b1[1]);
            mma_tf32(acc[0][3], a0, b1[2], b1[3]);
            mma_tf32(acc[1][0], a1, b0[0], b0[1]);
            mma_tf32(acc[1][1], a1, b0[2], b0[3]);
            mma_tf32(acc[1][2], a1, b1[0], b1[1]);
            mma_tf32(acc[1][3], a1, b1[2], b1[3]);
        }
        __syncthreads();
    }

    // means: each row's full-K sum lives in a thread pair
    rowsum += __shfl_xor_sync(0xffffffffu, rowsum, 1);
    if ((t & 1) == 0) mu[row] = rowsum * (1.0f / (float)Mn);
    __syncthreads();

    // epilogue: y = acc/M - mu_r * mu_c, direct to output
    const float invM = 1.0f / (float)Mn;
    float* yb = y + (size_t)b * Cn * Cn;
#pragma unroll
    for (int im = 0; im < 2; im++) {
        const int r0 = wm + im * 16 + g;
        const float mr0 = mu[r0];
        const float mr1 = mu[r0 + 8];
#pragma unroll
        for (int in = 0; in < 4; in++) {
            const int c0 = wn + in * 8 + 2 * tg;
            const float mc0 = mu[c0];
            const float mc1 = mu[c0 + 1];
            float2 o0, o1;
            o0.x = acc[im][in][0] * invM - mr0 * mc0;
            o0.y = acc[im][in][1] * invM - mr0 * mc1;
            o1.x = acc[im][in][2] * invM - mr1 * mc0;
            o1.y = acc[im][in][3] * invM - mr1 * mc1;
            *(float2*)(yb + (size_t)r0 * Cn + c0)       = o0;
            *(float2*)(yb + (size_t)(r0 + 8) * Cn + c0) = o1;
        }
    }
}

extern "C" void kernel_launch(void* const* d_in, const int* in_sizes, int n_in,
                              void* d_out, int out_size) {
    (void)in_sizes; (void)n_in; (void)out_size;
    const float* x = (const float*)d_in[0];
    float* y = (float*)d_out;
    covpool_fused<<<2 * Bn, 256>>>(x, y);
}

// round 4
// speedup vs baseline: 1.4307x; 1.4307x over previous
#include <cuda_runtime.h>
#include <cstdint>

// Covariance pooling: y[b] = (1/M) X Xᵀ - μ μᵀ, X = x[b] as [C=128, M=4096].
// Kernel 1 (partial): 128 CTAs = 64 batches x 2 K-halves; 128 threads; 4 warps
//   of 64x64 tiles (1.0 smem-wavefront per MMA); cp.async 4-stage pipeline;
//   raw-fp32 operands into tf32 mma.sync (HW truncation, debiased by CORR);
//   exact fp32 row sums via an in-pipeline LDS pass.
// Kernel 2 (finish): 256 CTAs combine K-halves, scale, subtract mean outer product.

#define DINLINE __device__ __forceinline__

static constexpr int Bn = 64;
static constexpr int Cn = 128;
static constexpr int Mn = 4096;
static constexpr int KHALF = Mn / 2;       // 2048
static constexpr int KT = 32;              // k floats per tile
static constexpr int NKT = KHALF / KT;     // 64 tiles
static constexpr int PAD = 36;             // floats per SMEM row
static constexpr int PADB = PAD * 4;       // 144 bytes
static constexpr int STAGES = 4;
static constexpr int STAGE_B = Cn * PADB;  // 18432 bytes
static constexpr int SMEM_B = STAGES * STAGE_B;  // 73728

// tf32 truncation debias: 1/(1 - 2 * 2^-11 * (1/(2 ln 2)))
static constexpr float CORR = 1.00070466f;

__device__ float g_part[2 * Bn][Cn * Cn];
__device__ float g_sums[2 * Bn][Cn];

DINLINE void mma_tf32(float d[4], const uint32_t a[4], uint32_t b0, uint32_t b1) {
    asm volatile(
        "mma.sync.aligned.m16n8k8.row.col.f32.tf32.tf32.f32 "
        "{%0,%1,%2,%3}, {%4,%5,%6,%7}, {%8,%9}, {%0,%1,%2,%3};"
        : "+f"(d[0]), "+f"(d[1]), "+f"(d[2]), "+f"(d[3])
        : "r"(a[0]), "r"(a[1]), "r"(a[2]), "r"(a[3]), "r"(b0), "r"(b1));
}
DINLINE void ldsm_x4(uint32_t r[4], uint32_t addr) {
    asm volatile("ldmatrix.sync.aligned.m8n8.x4.shared.b16 {%0,%1,%2,%3}, [%4];"
                 : "=r"(r[0]), "=r"(r[1]), "=r"(r[2]), "=r"(r[3]) : "r"(addr));
}
DINLINE uint32_t smem_u32(const void* p) {
    uint32_t a;
    asm("{ .reg .u64 t; cvta.to.shared.u64 t, %1; cvt.u32.u64 %0, t; }"
        : "=r"(a) : "l"(p));
    return a;
}
DINLINE void cp16(uint32_t dst, const void* src) {
    asm volatile("cp.async.cg.shared.global [%0], [%1], 16;"
                 :: "r"(dst), "l"(src) : "memory");
}
DINLINE void cp_commit() { asm volatile("cp.async.commit_group;" ::: "memory"); }
template <int N> DINLINE void cp_wait() {
    asm volatile("cp.async.wait_group %0;" :: "n"(N) : "memory");
}

__global__ __launch_bounds__(128, 1)
void covpool_partial(const float* __restrict__ x) {
    extern __shared__ char smem[];
    const uint32_t sb = smem_u32(smem);

    const int t    = threadIdx.x;
    const int warp = t >> 5;
    const int lane = t & 31;
    const int cta  = blockIdx.x;        // 0..127
    const int s    = cta & 1;
    const int b    = cta >> 1;

    // loader: one row per thread, 128 B per tile
    const float* xrow = x + (size_t)b * Cn * Mn + (size_t)t * Mn + (size_t)s * KHALF;
    const uint32_t ldst = (uint32_t)(t * PADB);

    // warp tile 64x64, 2x2 warp grid
    const int wm = (warp & 1) * 64;
    const int wn = (warp >> 1) * 64;
    const int g  = lane >> 2;
    const int tg = lane & 3;

    // ldmatrix lane offsets
    const uint32_t aoff = (uint32_t)((wm + (lane & 15)) * PADB + (lane >> 4) * 16);
    const uint32_t boff = (uint32_t)((wn + (lane & 7) + ((lane >> 4) * 8)) * PADB
                                     + ((lane >> 3) & 1) * 16);

    float acc[4][8][4];
#pragma unroll
    for (int im = 0; im < 4; im++)
#pragma unroll
        for (int in = 0; in < 8; in++)
#pragma unroll
            for (int j = 0; j < 4; j++) acc[im][in][j] = 0.0f;

    float rowsum = 0.0f;

    // prologue: stages 0..2
#pragma unroll
    for (int p = 0; p < STAGES - 1; p++) {
        const uint32_t d0 = sb + p * STAGE_B + ldst;
        const float* src = xrow + p * KT;
#pragma unroll
        for (int i = 0; i < 8; i++) cp16(d0 + i * 16, src + i * 4);
        cp_commit();
    }

    for (int kt = 0; kt < NKT; kt++) {
        cp_wait<STAGES - 2>();
        __syncthreads();
        // issue stage kt+3
        if (kt + STAGES - 1 < NKT) {
            const uint32_t d0 = sb + ((kt + STAGES - 1) & (STAGES - 1)) * STAGE_B + ldst;
            const float* src = xrow + (kt + STAGES - 1) * KT;
#pragma unroll
            for (int i = 0; i < 8; i++) cp16(d0 + i * 16, src + i * 4);
        }
        cp_commit();

        const uint32_t base = sb + (kt & (STAGES - 1)) * STAGE_B;

        // row sum: this thread's own row (raw fp32, exact)
#pragma unroll
        for (int i = 0; i < 8; i++) {
            float4 v = *(const float4*)(smem + (kt & (STAGES - 1)) * STAGE_B
                                        + t * PADB + i * 16);
            rowsum += v.x + v.y + v.z + v.w;
        }

#pragma unroll
        for (int ks = 0; ks < 4; ks++) {
            const uint32_t k0 = ks * 32;   // bytes within row
            uint32_t A[4][4], Bf[4][4];
#pragma unroll
            for (int im = 0; im < 4; im++)
                ldsm_x4(A[im], base + aoff + im * 16 * PADB + k0);
#pragma unroll
            for (int jn = 0; jn < 4; jn++)
                ldsm_x4(Bf[jn], base + boff + jn * 16 * PADB + k0);
#pragma unroll
            for (int im = 0; im < 4; im++)
#pragma unroll
                for (int jn = 0; jn < 4; jn++) {
                    mma_tf32(acc[im][2 * jn],     A[im], Bf[jn][0], Bf[jn][1]);
                    mma_tf32(acc[im][2 * jn + 1], A[im], Bf[jn][2], Bf[jn][3]);
                }
        }
    }

    // epilogue: partial Gram + row sums to scratch
    float* gp = g_part[cta];
#pragma unroll
    for (int im = 0; im < 4; im++) {
        const int r0 = wm + im * 16 + g;
#pragma unroll
        for (int in = 0; in < 8; in++) {
            const int c0 = wn + in * 8 + 2 * tg;
            *(float2*)(gp + (size_t)r0 * Cn + c0) =
                make_float2(acc[im][in][0], acc[im][in][1]);
            *(float2*)(gp + (size_t)(r0 + 8) * Cn + c0) =
                make_float2(acc[im][in][2], acc[im][in][3]);
        }
    }
    g_sums[cta][t] = rowsum;
}

__global__ __launch_bounds__(256, 2)
void covpool_finish(float* __restrict__ y) {
    __shared__ float mu[Cn];
    const int t   = threadIdx.x;
    const int blk = blockIdx.x;
    const int b   = blk >> 2;
    const int q   = blk & 3;
    if (t < Cn)
        mu[t] = (g_sums[2 * b][t] + g_sums[2 * b + 1][t]) * (1.0f / (float)Mn);
    __syncthreads();

    const float4* G0 = (const float4*)g_part[2 * b];
    const float4* G1 = (const float4*)g_part[2 * b + 1];
    float4* out = (float4*)(y + (size_t)b * Cn * Cn);
    const float4* mu4 = (const float4*)mu;
    const float a = CORR * (1.0f / (float)Mn);
#pragma unroll
    for (int j = 0; j < 4; j++) {
        const int idx = q * 1024 + t + j * 256;   // float4 index in [0,4096)
        const int r   = idx >> 5;
        const float mr = mu[r];
        const float4 m = mu4[idx & 31];
        const float4 p = G0[idx];
        const float4 c = G1[idx];
        float4 o;
        o.x = (p.x + c.x) * a - mr * m.x;
        o.y = (p.y + c.y) * a - mr * m.y;
        o.z = (p.z + c.z) * a - mr * m.z;
        o.w = (p.w + c.w) * a - mr * m.w;
        out[idx] = o;
    }
}

extern "C" void kernel_launch(void* const* d_in, const int* in_sizes, int n_in,
                              void* d_out, int out_size) {
    (void)in_sizes; (void)n_in; (void)out_size;
    const float* x = (const float*)d_in[0];
    float* y = (float*)d_out;
    cudaFuncSetAttribute(covpool_partial,
                         cudaFuncAttributeMaxDynamicSharedMemorySize, SMEM_B);
    covpool_partial<<<2 * Bn, 128, SMEM_B>>>(x);
    covpool_finish<<<4 * Bn, 256>>>(y);
}